// round 1
// baseline (speedup 1.0000x reference)
#include <cuda_runtime.h>
#include <cstdint>

// Problem constants (fixed by setup_inputs): B=1, H=32, Lq=512, Lk=4096, group_size=4
#define H       32
#define LQ      512
#define LK      4096
#define WORDS   128            // LK / 32
#define KSEL    819            // int(0.2 * 4096)
#define THRESH  1638           // min(2*819, int(0.75*4096))
#define GS      4
#define NG      8              // H / GS
#define NOT_CHOSEN (1 << 30)

// Scratch (device globals; no allocation allowed)
__device__ unsigned           g_masks[(size_t)H * LQ * WORDS];   // 8 MB of top-k bitsets
__device__ int                g_nsel[H];
__device__ unsigned           g_hunion[H * WORDS];
__device__ unsigned long long g_count;

// Order-preserving float -> uint32 map (larger float => larger key)
__device__ __forceinline__ unsigned fkey(float f) {
    unsigned u = __float_as_uint(f);
    return (u & 0x80000000u) ? ~u : (u | 0x80000000u);
}

// ---------------------------------------------------------------------------
// Kernel 1: per-row exact top-k membership mask via 4-pass radix select.
// grid = H*LQ blocks, 256 threads. Each block owns one row of 4096 floats.
// ---------------------------------------------------------------------------
__global__ void k_topk(const float* __restrict__ scores) {
    __shared__ unsigned skey[LK];
    __shared__ unsigned hist[256];
    __shared__ unsigned s_prefix, s_rem;

    const int row = blockIdx.x;
    const int t   = threadIdx.x;

    // Load + convert (vectorized, coalesced)
    const float4* src = (const float4*)(scores + (size_t)row * LK);
    #pragma unroll
    for (int i = 0; i < 4; i++) {
        int idx = t + i * 256;
        float4 v = src[idx];
        int b = idx * 4;
        skey[b + 0] = fkey(v.x);
        skey[b + 1] = fkey(v.y);
        skey[b + 2] = fkey(v.z);
        skey[b + 3] = fkey(v.w);
    }
    if (t == 0) { s_prefix = 0u; s_rem = KSEL; }

    // Radix select: find the KSEL-th largest key (pivot), MSB byte first
    for (int pass = 3; pass >= 0; --pass) {
        hist[t] = 0u;
        __syncthreads();
        const unsigned prefix = s_prefix;
        const int sh = pass * 8;
        #pragma unroll
        for (int i = 0; i < 16; i++) {
            unsigned key = skey[t + i * 256];
            bool match = (pass == 3) ? true : ((key >> (sh + 8)) == prefix);
            if (match) atomicAdd(&hist[(key >> sh) & 0xFFu], 1u);
        }
        __syncthreads();
        if (t == 0) {
            unsigned rem = s_rem, cum = 0;
            int b = 255;
            for (;;) {
                cum += hist[b];
                if (cum >= rem || b == 0) break;
                --b;
            }
            s_rem    = rem - (cum - hist[b]);   // rank within selected bucket
            s_prefix = (prefix << 8) | (unsigned)b;
        }
        __syncthreads();
    }
    const unsigned pivot = s_prefix;

    // Emit membership bitset via ballot (bit = column index)
    const int warp = t >> 5, lane = t & 31;
    unsigned* dst = g_masks + (size_t)row * WORDS;
    #pragma unroll
    for (int i = 0; i < 16; i++) {
        int e = i * 256 + warp * 32 + lane;
        unsigned bal = __ballot_sync(0xffffffffu, skey[e] >= pivot);
        if (lane == 0) dst[e >> 5] = bal;
    }
}

// ---------------------------------------------------------------------------
// Kernel 2: per-head back-to-front union scan; first n with |union| >= THRESH.
// grid = H blocks, 128 threads (thread t owns bitset word t).
// Statistically exits at n ~ 3.
// ---------------------------------------------------------------------------
__global__ void k_scan() {
    const int h = blockIdx.x, t = threadIdx.x;
    const int lane = t & 31, warp = t >> 5;
    __shared__ int s_found, s_cnt;
    __shared__ int ws[4];
    if (t == 0) { s_found = 0; s_cnt = 0; if (h == 0) g_count = 0ull; }
    __syncthreads();

    const unsigned* base = g_masks + (size_t)h * LQ * WORDS;
    unsigned un = 0;
    for (int n = 1; n <= LQ; n++) {
        unsigned m = base[(size_t)(LQ - n) * WORDS + t];
        int add = __popc(m & ~un);
        un |= m;
        #pragma unroll
        for (int off = 16; off; off >>= 1)
            add += __shfl_down_sync(0xffffffffu, add, off);
        if (lane == 0) ws[warp] = add;
        __syncthreads();
        if (t == 0) {
            s_cnt += ws[0] + ws[1] + ws[2] + ws[3];
            if (!s_found && s_cnt >= THRESH) s_found = n;
        }
        __syncthreads();
        if (s_found) break;
    }
    if (t == 0) g_nsel[h] = s_found ? s_found : NOT_CHOSEN;
}

// ---------------------------------------------------------------------------
// Kernel 3: compute global n_stop, per-head union of last n_stop rows.
// grid = H blocks, 128 threads.
// ---------------------------------------------------------------------------
__global__ void k_final() {
    __shared__ int s_nstop;
    const int h = blockIdx.x, t = threadIdx.x;
    if (t == 0) {
        bool all = true;
        int mx = 1;
        for (int i = 0; i < H; i++) {
            int v = g_nsel[i];
            if (v >= NOT_CHOSEN) all = false;
            else if (v > mx) mx = v;
        }
        s_nstop = all ? mx : LQ;
    }
    __syncthreads();
    const int ns = s_nstop;
    const unsigned* base = g_masks + (size_t)h * LQ * WORDS;
    unsigned un = 0;
    for (int n = 1; n <= ns; n++)
        un |= base[(size_t)(LQ - n) * WORDS + t];
    g_hunion[h * WORDS + t] = un;
}

// ---------------------------------------------------------------------------
// Kernel 4: group-OR, write last-row mask values, accumulate density count.
// grid = NG blocks, 128 threads.
// ---------------------------------------------------------------------------
__global__ void k_out(float* __restrict__ out) {
    __shared__ unsigned su[WORDS];
    __shared__ int ws[4];
    const int g = blockIdx.x, t = threadIdx.x;
    const int lane = t & 31, warp = t >> 5;

    unsigned u = g_hunion[(g * GS + 0) * WORDS + t]
               | g_hunion[(g * GS + 1) * WORDS + t]
               | g_hunion[(g * GS + 2) * WORDS + t]
               | g_hunion[(g * GS + 3) * WORDS + t];
    su[t] = u;

    int c = __popc(u);
    #pragma unroll
    for (int off = 16; off; off >>= 1)
        c += __shfl_down_sync(0xffffffffu, c, off);
    if (lane == 0) ws[warp] = c;
    __syncthreads();
    if (t == 0)
        atomicAdd(&g_count, (unsigned long long)(GS * (ws[0] + ws[1] + ws[2] + ws[3])));

    const float MINV = -3.402823466e38f;  // finfo(float32).min
    for (int col = t; col < LK; col += 128) {
        float val = ((su[col >> 5] >> (col & 31)) & 1u) ? 0.0f : MINV;
        #pragma unroll
        for (int hh = 0; hh < GS; hh++) {
            size_t off = ((size_t)(g * GS + hh) * LQ + (LQ - 1)) * LK + col;
            out[off] = val;
        }
    }
}

__global__ void k_density(float* __restrict__ out) {
    out[(size_t)H * LQ * LK] = (float)g_count / (float)(H * LK);
}

// ---------------------------------------------------------------------------
extern "C" void kernel_launch(void* const* d_in, const int* in_sizes, int n_in,
                              void* d_out, int out_size) {
    const float* scores = (const float*)d_in[0];
    float* out = (float*)d_out;

    // Bulk of output is zeros (all query rows except the last)
    cudaMemsetAsync(d_out, 0, (size_t)out_size * sizeof(float), 0);

    k_topk<<<H * LQ, 256>>>(scores);
    k_scan<<<H, 128>>>();
    k_final<<<H, 128>>>();
    k_out<<<NG, 128>>>(out);
    if (out_size > H * LQ * LK)
        k_density<<<1, 1>>>(out);
}

// round 2
// speedup vs baseline: 1.4378x; 1.4378x over previous
#include <cuda_runtime.h>
#include <cstdint>

// Problem constants (fixed by setup_inputs): B=1, H=32, Lq=512, Lk=4096, group_size=4
#define H       32
#define LQ      512
#define LK      4096
#define WORDS   128            // LK / 32
#define KSEL    819            // int(0.2 * 4096)
#define THRESH  1638           // min(2*819, int(0.75*4096))
#define GS      4
#define NG      8              // H / GS
#define NOT_CHOSEN (1 << 30)
#define NBINS   4096           // 12-bit first-pass radix
#define MAXCAND 512

// Scratch (device globals; no allocation allowed)
__device__ unsigned           g_masks[(size_t)H * LQ * WORDS];   // 8 MB of top-k bitsets
__device__ int                g_nsel[H];
__device__ unsigned           g_hunion[H * WORDS];
__device__ unsigned long long g_count;

// Order-preserving float -> uint32 map (larger float => larger key)
__device__ __forceinline__ unsigned fkey(float f) {
    unsigned u = __float_as_uint(f);
    return (u & 0x80000000u) ? ~u : (u | 0x80000000u);
}

// ---------------------------------------------------------------------------
// Kernel 1: per-row exact top-k mask, single 12-bit histogram + refinement.
// Also zeros this row of the output (folds the big memset into the
// bandwidth-bound kernel so reads and writes overlap).
// grid = H*LQ blocks, 256 threads; each block owns one row of 4096 floats.
// ---------------------------------------------------------------------------
__global__ void __launch_bounds__(256) k_topk(const float* __restrict__ scores,
                                              float* __restrict__ out) {
    __shared__ unsigned hist[NBINS];        // 16 KB
    __shared__ unsigned chunk_suffix[256];
    __shared__ unsigned cand[MAXCAND];      // 2 KB
    __shared__ unsigned char snib[1024];    // 1 KB: 4-bit membership nibbles
    __shared__ unsigned s_cnt, s_bucket, s_rem, s_pivot;

    const int row = blockIdx.x;
    const int t   = threadIdx.x;

    #pragma unroll
    for (int i = 0; i < NBINS / 256; i++) hist[t + i * 256] = 0u;
    if (t == 0) s_cnt = 0u;
    __syncthreads();

    // Load 16 elements/thread into registers (coalesced float4)
    unsigned key[16];
    const float4* src  = (const float4*)(scores + (size_t)row * LK);
    float4*       zdst = (float4*)(out + (size_t)row * LK);
    #pragma unroll
    for (int i = 0; i < 4; i++) {
        float4 v = src[t + i * 256];
        key[4 * i + 0] = fkey(v.x);
        key[4 * i + 1] = fkey(v.y);
        key[4 * i + 2] = fkey(v.z);
        key[4 * i + 3] = fkey(v.w);
    }

    // Zero this row of the output (last rows get overwritten by k_out later)
    const float4 z = make_float4(0.f, 0.f, 0.f, 0.f);
    #pragma unroll
    for (int i = 0; i < 4; i++) zdst[t + i * 256] = z;

    // 12-bit histogram (single pass, spread bins -> low smem-atomic contention)
    #pragma unroll
    for (int e = 0; e < 16; e++) atomicAdd(&hist[key[e] >> 20], 1u);
    __syncthreads();

    // Two-level suffix count: thread t owns bins [16t, 16t+16)
    unsigned csum = 0;
    #pragma unroll
    for (int i = 0; i < 16; i++) csum += hist[t * 16 + i];
    chunk_suffix[t] = csum;
    __syncthreads();
    // Hillis-Steele suffix scan over the 256 chunk sums
    #pragma unroll
    for (int s = 1; s < 256; s <<= 1) {
        unsigned v = (t + s < 256) ? chunk_suffix[t + s] : 0u;
        __syncthreads();
        chunk_suffix[t] += v;
        __syncthreads();
    }

    // Locate the bucket where cumulative-from-top crosses KSEL (unique thread)
    {
        unsigned above = (t < 255) ? chunk_suffix[t + 1] : 0u;
        if (above < KSEL && chunk_suffix[t] >= KSEL) {
            unsigned acc = above;
            #pragma unroll
            for (int i = 15; i >= 0; --i) {
                unsigned hv = hist[t * 16 + i];
                if (acc + hv >= KSEL) { s_bucket = (unsigned)(t * 16 + i); s_rem = KSEL - acc; break; }
                acc += hv;
            }
        }
    }
    __syncthreads();
    const unsigned bucket = s_bucket;
    const unsigned rem    = s_rem;

    // Compact candidates that fall in the pivot bucket (expected ~124)
    #pragma unroll
    for (int e = 0; e < 16; e++) {
        if ((key[e] >> 20) == bucket) {
            unsigned p = atomicAdd(&s_cnt, 1u);
            if (p < MAXCAND) cand[p] = key[e];
        }
    }
    __syncthreads();
    const unsigned nc = min(s_cnt, (unsigned)MAXCAND);

    // Rank-select the rem-th largest candidate: O(nc^2) spread over threads
    if (t < (int)nc) {
        unsigned me = cand[t];
        unsigned g = 0, eq = 0;
        for (unsigned j = 0; j < nc; j++) {
            unsigned v = cand[j];
            g  += (v > me);
            eq += (v == me);
        }
        if (g < rem && g + eq >= rem) s_pivot = me;
    }
    __syncthreads();
    const unsigned pivot = s_pivot;

    // Membership nibbles: nib[n] holds bits for elements [4n, 4n+4)
    #pragma unroll
    for (int i = 0; i < 4; i++) {
        unsigned nib = 0;
        #pragma unroll
        for (int m = 0; m < 4; m++) nib |= (unsigned)(key[4 * i + m] >= pivot) << m;
        snib[t + i * 256] = (unsigned char)nib;
    }
    __syncthreads();

    // Pack 8 nibbles -> one 32-bit mask word; 128 words per row
    if (t < 128) {
        unsigned lo = *(const unsigned*)&snib[8 * t];
        unsigned hi = *(const unsigned*)&snib[8 * t + 4];
        unsigned w =  (lo         & 0xFu)
                   | ((lo >>  8)  & 0xFu) << 4
                   | ((lo >> 16)  & 0xFu) << 8
                   | ((lo >> 24)  & 0xFu) << 12
                   | ( hi         & 0xFu) << 16
                   | ((hi >>  8)  & 0xFu) << 20
                   | ((hi >> 16)  & 0xFu) << 24
                   | ((hi >> 24)  & 0xFu) << 28;
        g_masks[(size_t)row * WORDS + t] = w;
    }
}

// ---------------------------------------------------------------------------
// Kernel 2: per-head back-to-front union scan; first n with |union| >= THRESH.
// grid = H blocks, 128 threads (thread t owns bitset word t).
// Statistically exits at n ~ 3.
// ---------------------------------------------------------------------------
__global__ void k_scan() {
    const int h = blockIdx.x, t = threadIdx.x;
    const int lane = t & 31, warp = t >> 5;
    __shared__ int s_found, s_cnt;
    __shared__ int ws[4];
    if (t == 0) { s_found = 0; s_cnt = 0; if (h == 0) g_count = 0ull; }
    __syncthreads();

    const unsigned* base = g_masks + (size_t)h * LQ * WORDS;
    unsigned un = 0;
    for (int n = 1; n <= LQ; n++) {
        unsigned m = base[(size_t)(LQ - n) * WORDS + t];
        int add = __popc(m & ~un);
        un |= m;
        #pragma unroll
        for (int off = 16; off; off >>= 1)
            add += __shfl_down_sync(0xffffffffu, add, off);
        if (lane == 0) ws[warp] = add;
        __syncthreads();
        if (t == 0) {
            s_cnt += ws[0] + ws[1] + ws[2] + ws[3];
            if (!s_found && s_cnt >= THRESH) s_found = n;
        }
        __syncthreads();
        if (s_found) break;
    }
    if (t == 0) g_nsel[h] = s_found ? s_found : NOT_CHOSEN;
}

// ---------------------------------------------------------------------------
// Kernel 3: compute global n_stop, per-head union of last n_stop rows.
// grid = H blocks, 128 threads.
// ---------------------------------------------------------------------------
__global__ void k_final() {
    __shared__ int s_nstop;
    const int h = blockIdx.x, t = threadIdx.x;
    if (t == 0) {
        bool all = true;
        int mx = 1;
        for (int i = 0; i < H; i++) {
            int v = g_nsel[i];
            if (v >= NOT_CHOSEN) all = false;
            else if (v > mx) mx = v;
        }
        s_nstop = all ? mx : LQ;
    }
    __syncthreads();
    const int ns = s_nstop;
    const unsigned* base = g_masks + (size_t)h * LQ * WORDS;
    unsigned un = 0;
    for (int n = 1; n <= ns; n++)
        un |= base[(size_t)(LQ - n) * WORDS + t];
    g_hunion[h * WORDS + t] = un;
}

// ---------------------------------------------------------------------------
// Kernel 4: group-OR, write last-row mask values, accumulate density count.
// grid = NG blocks, 128 threads.
// ---------------------------------------------------------------------------
__global__ void k_out(float* __restrict__ out) {
    __shared__ unsigned su[WORDS];
    __shared__ int ws[4];
    const int g = blockIdx.x, t = threadIdx.x;
    const int lane = t & 31, warp = t >> 5;

    unsigned u = g_hunion[(g * GS + 0) * WORDS + t]
               | g_hunion[(g * GS + 1) * WORDS + t]
               | g_hunion[(g * GS + 2) * WORDS + t]
               | g_hunion[(g * GS + 3) * WORDS + t];
    su[t] = u;

    int c = __popc(u);
    #pragma unroll
    for (int off = 16; off; off >>= 1)
        c += __shfl_down_sync(0xffffffffu, c, off);
    if (lane == 0) ws[warp] = c;
    __syncthreads();
    if (t == 0)
        atomicAdd(&g_count, (unsigned long long)(GS * (ws[0] + ws[1] + ws[2] + ws[3])));

    const float MINV = -3.402823466e38f;  // finfo(float32).min
    for (int col = t; col < LK; col += 128) {
        float val = ((su[col >> 5] >> (col & 31)) & 1u) ? 0.0f : MINV;
        #pragma unroll
        for (int hh = 0; hh < GS; hh++) {
            size_t off = ((size_t)(g * GS + hh) * LQ + (LQ - 1)) * LK + col;
            out[off] = val;
        }
    }
}

__global__ void k_density(float* __restrict__ out) {
    out[(size_t)H * LQ * LK] = (float)g_count / (float)(H * LK);
}

// ---------------------------------------------------------------------------
extern "C" void kernel_launch(void* const* d_in, const int* in_sizes, int n_in,
                              void* d_out, int out_size) {
    const float* scores = (const float*)d_in[0];
    float* out = (float*)d_out;

    k_topk<<<H * LQ, 256>>>(scores, out);   // also zeros the output rows
    k_scan<<<H, 128>>>();
    k_final<<<H, 128>>>();
    k_out<<<NG, 128>>>(out);
    if (out_size > H * LQ * LK)
        k_density<<<1, 1>>>(out);
}

// round 3
// speedup vs baseline: 2.8161x; 1.9586x over previous
#include <cuda_runtime.h>
#include <cstdint>

// Problem constants (fixed by setup_inputs): B=1, H=32, Lq=512, Lk=4096, group_size=4
#define H       32
#define LQ      512
#define LK      4096
#define WORDS   128            // LK / 32
#define KSEL    819            // int(0.2 * 4096)
#define THRESH  1638           // min(2*819, int(0.75*4096))
#define GS      4
#define NG      8              // H / GS
#define NOT_CHOSEN (1 << 30)
#define MAXCAND 256

// Statistical window for the 819th-largest of 4096 i.i.d. N(0,1) samples.
// Quantile = 0.8416, sd of the order statistic ~0.022 -> [0.70, 1.00] is ~7 sigma.
// Exact fallback path handles anything outside the window.
#define WLO 0.70f
#define WHI 1.00f
#define WSCALE (256.0f / (WHI - WLO))

// Scratch (device globals; no allocation allowed)
__device__ unsigned           g_masks[(size_t)H * LQ * WORDS];   // 8 MB of top-k bitsets
__device__ int                g_nsel[H];
__device__ unsigned           g_hunion[H * WORDS];
__device__ unsigned long long g_count;

// Order-preserving float -> uint32 map (larger float => larger key)
__device__ __forceinline__ unsigned fkey(float f) {
    unsigned u = __float_as_uint(f);
    return (u & 0x80000000u) ? ~u : (u | 0x80000000u);
}

// ---------------------------------------------------------------------------
// Kernel 1: per-row exact top-k mask via windowed 256-bin histogram around the
// statistically-known pivot location + exact candidate refinement, with an
// exact 32-step binary-search fallback. Also zeros this row of the output.
// grid = H*LQ blocks, 256 threads; each block owns one row of 4096 floats.
// ---------------------------------------------------------------------------
__global__ void __launch_bounds__(256) k_topk(const float* __restrict__ scores,
                                              float* __restrict__ out) {
    __shared__ unsigned hist[256];          // 1 KB windowed histogram
    __shared__ unsigned cand[MAXCAND];      // pivot-bin candidates (fkey)
    __shared__ unsigned char snib[1024];    // 4-bit membership nibbles
    __shared__ unsigned s_cnthi, s_ncand, s_pivotkey, s_tot;
    __shared__ int s_bin, s_rem;

    const int row = blockIdx.x;
    const int t   = threadIdx.x;
    const int lane = t & 31, warp = t >> 5;

    hist[t] = 0u;
    if (t == 0) { s_cnthi = 0u; s_ncand = 0u; s_bin = -2; }
    __syncthreads();

    // Load 16 elements/thread (coalesced float4); zero the output row.
    float x[16];
    const float4* src  = (const float4*)(scores + (size_t)row * LK);
    float4*       zdst = (float4*)(out + (size_t)row * LK);
    #pragma unroll
    for (int i = 0; i < 4; i++) {
        float4 v = src[t + i * 256];
        x[4 * i + 0] = v.x; x[4 * i + 1] = v.y;
        x[4 * i + 2] = v.z; x[4 * i + 3] = v.w;
    }
    const float4 z = make_float4(0.f, 0.f, 0.f, 0.f);
    #pragma unroll
    for (int i = 0; i < 4; i++) zdst[t + i * 256] = z;

    // Count above-window; histogram only the in-window elements (~8% of row)
    int chi = 0;
    #pragma unroll
    for (int e = 0; e < 16; e++) {
        float v = x[e];
        if (v > WHI) {
            chi++;
        } else if (v >= WLO) {
            int b = (int)((WHI - v) * WSCALE);
            if (b > 255) b = 255;
            atomicAdd(&hist[b], 1u);
        }
    }
    #pragma unroll
    for (int off = 16; off; off >>= 1)
        chi += __shfl_down_sync(0xffffffffu, chi, off);
    if (lane == 0) atomicAdd(&s_cnthi, (unsigned)chi);
    __syncthreads();

    // One-warp prefix scan over the 256 bins (bin 0 = largest values)
    if (warp == 0) {
        const unsigned cnthi = s_cnthi;
        unsigned part = 0;
        #pragma unroll
        for (int i = 0; i < 8; i++) part += hist[lane * 8 + i];
        // exclusive prefix of 8-bin chunk sums across lanes
        unsigned pfx = part;
        #pragma unroll
        for (int s = 1; s < 32; s <<= 1) {
            unsigned v = __shfl_up_sync(0xffffffffu, pfx, s);
            if (lane >= s) pfx += v;
        }
        unsigned excl = pfx - part;            // sum of chunks before this lane
        unsigned total = __shfl_sync(0xffffffffu, pfx, 31);
        if (lane == 0) s_tot = total;
        // does KSEL cross inside this lane's chunk?
        unsigned base = cnthi + excl;
        if (base < KSEL && base + part >= KSEL) {
            unsigned acc = base;
            #pragma unroll
            for (int i = 0; i < 8; i++) {
                unsigned hv = hist[lane * 8 + i];
                if (acc + hv >= KSEL) { s_bin = lane * 8 + i; s_rem = (int)(KSEL - acc); break; }
                acc += hv;
            }
        }
        if (lane == 0 && (cnthi >= KSEL || cnthi + total < KSEL)) s_bin = -1; // fallback
    }
    __syncthreads();

    const int bin = s_bin;

    if (bin >= 0) {
        // ---- fast path: gather candidates in the pivot bin, exact rank-select
        #pragma unroll
        for (int e = 0; e < 16; e++) {
            float v = x[e];
            if (v <= WHI && v >= WLO) {
                int b = (int)((WHI - v) * WSCALE);
                if (b > 255) b = 255;
                if (b == bin) {
                    unsigned p = atomicAdd(&s_ncand, 1u);
                    if (p < MAXCAND) cand[p] = fkey(v);
                }
            }
        }
        __syncthreads();
        unsigned nc = s_ncand;
        if (nc <= MAXCAND) {
            const int rem = s_rem;
            if (t < (int)nc) {
                unsigned me = cand[t];
                int gcnt = 0, eq = 0;
                for (unsigned j = 0; j < nc; j++) {
                    unsigned v = cand[j];
                    gcnt += (v > me);
                    eq   += (v == me);
                }
                if (gcnt < rem && gcnt + eq >= rem) s_pivotkey = me;
            }
        } else {
            if (t == 0) s_bin = -1;   // overflow -> fallback
        }
        __syncthreads();
    }

    if (s_bin < 0) {
        // ---- exact fallback: MSB-first binary search on order-preserving keys
        unsigned piv = 0;
        for (int bit = 31; bit >= 0; --bit) {
            unsigned candv = piv | (1u << bit);
            int c = 0;
            #pragma unroll
            for (int e = 0; e < 16; e++) c += (fkey(x[e]) >= candv);
            #pragma unroll
            for (int off = 16; off; off >>= 1)
                c += __shfl_down_sync(0xffffffffu, c, off);
            if (t == 0) s_tot = 0u;
            __syncthreads();
            if (lane == 0) atomicAdd(&s_tot, (unsigned)c);
            __syncthreads();
            if (s_tot >= KSEL) piv = candv;
            __syncthreads();
        }
        if (t == 0) s_pivotkey = piv;
        __syncthreads();
    }

    const unsigned pivot = s_pivotkey;

    // Membership nibbles: nib[n] holds bits for elements [4n, 4n+4)
    #pragma unroll
    for (int i = 0; i < 4; i++) {
        unsigned nib = 0;
        #pragma unroll
        for (int m = 0; m < 4; m++) nib |= (unsigned)(fkey(x[4 * i + m]) >= pivot) << m;
        snib[t + i * 256] = (unsigned char)nib;
    }
    __syncthreads();

    // Pack 8 nibbles -> one 32-bit mask word; 128 words per row
    if (t < 128) {
        unsigned lo = *(const unsigned*)&snib[8 * t];
        unsigned hi = *(const unsigned*)&snib[8 * t + 4];
        unsigned w =  (lo         & 0xFu)
                   | ((lo >>  8)  & 0xFu) << 4
                   | ((lo >> 16)  & 0xFu) << 8
                   | ((lo >> 24)  & 0xFu) << 12
                   | ( hi         & 0xFu) << 16
                   | ((hi >>  8)  & 0xFu) << 20
                   | ((hi >> 16)  & 0xFu) << 24
                   | ((hi >> 24)  & 0xFu) << 28;
        g_masks[(size_t)row * WORDS + t] = w;
    }
}

// ---------------------------------------------------------------------------
// Kernel 2: per-head back-to-front union scan; first n with |union| >= THRESH.
// grid = H blocks, 128 threads (thread t owns bitset word t). Exits at n ~ 3.
// ---------------------------------------------------------------------------
__global__ void k_scan() {
    const int h = blockIdx.x, t = threadIdx.x;
    const int lane = t & 31, warp = t >> 5;
    __shared__ int s_found, s_cnt;
    __shared__ int ws[4];
    if (t == 0) { s_found = 0; s_cnt = 0; if (h == 0) g_count = 0ull; }
    __syncthreads();

    const unsigned* base = g_masks + (size_t)h * LQ * WORDS;
    unsigned un = 0;
    for (int n = 1; n <= LQ; n++) {
        unsigned m = base[(size_t)(LQ - n) * WORDS + t];
        int add = __popc(m & ~un);
        un |= m;
        #pragma unroll
        for (int off = 16; off; off >>= 1)
            add += __shfl_down_sync(0xffffffffu, add, off);
        if (lane == 0) ws[warp] = add;
        __syncthreads();
        if (t == 0) {
            s_cnt += ws[0] + ws[1] + ws[2] + ws[3];
            if (!s_found && s_cnt >= THRESH) s_found = n;
        }
        __syncthreads();
        if (s_found) break;
    }
    if (t == 0) g_nsel[h] = s_found ? s_found : NOT_CHOSEN;
}

// ---------------------------------------------------------------------------
// Kernel 3: compute global n_stop, per-head union of last n_stop rows.
// grid = H blocks, 128 threads.
// ---------------------------------------------------------------------------
__global__ void k_final() {
    __shared__ int s_nstop;
    const int h = blockIdx.x, t = threadIdx.x;
    if (t == 0) {
        bool all = true;
        int mx = 1;
        for (int i = 0; i < H; i++) {
            int v = g_nsel[i];
            if (v >= NOT_CHOSEN) all = false;
            else if (v > mx) mx = v;
        }
        s_nstop = all ? mx : LQ;
    }
    __syncthreads();
    const int ns = s_nstop;
    const unsigned* base = g_masks + (size_t)h * LQ * WORDS;
    unsigned un = 0;
    for (int n = 1; n <= ns; n++)
        un |= base[(size_t)(LQ - n) * WORDS + t];
    g_hunion[h * WORDS + t] = un;
}

// ---------------------------------------------------------------------------
// Kernel 4: group-OR, write last-row mask values, accumulate density count.
// grid = (NG, 8); blockIdx.y selects a 512-column slice (more parallelism).
// ---------------------------------------------------------------------------
__global__ void k_out(float* __restrict__ out) {
    __shared__ unsigned su[WORDS];
    __shared__ int ws[4];
    const int g = blockIdx.x, slice = blockIdx.y, t = threadIdx.x;
    const int lane = t & 31, warp = t >> 5;

    unsigned u = g_hunion[(g * GS + 0) * WORDS + t]
               | g_hunion[(g * GS + 1) * WORDS + t]
               | g_hunion[(g * GS + 2) * WORDS + t]
               | g_hunion[(g * GS + 3) * WORDS + t];
    su[t] = u;

    if (slice == 0) {
        int c = __popc(u);
        #pragma unroll
        for (int off = 16; off; off >>= 1)
            c += __shfl_down_sync(0xffffffffu, c, off);
        if (lane == 0) ws[warp] = c;
    }
    __syncthreads();
    if (slice == 0 && t == 0)
        atomicAdd(&g_count, (unsigned long long)(GS * (ws[0] + ws[1] + ws[2] + ws[3])));

    const float MINV = -3.402823466e38f;  // finfo(float32).min
    #pragma unroll
    for (int j = 0; j < 4; j++) {
        int col = slice * 512 + j * 128 + t;
        float val = ((su[col >> 5] >> (col & 31)) & 1u) ? 0.0f : MINV;
        #pragma unroll
        for (int hh = 0; hh < GS; hh++) {
            size_t off = ((size_t)(g * GS + hh) * LQ + (LQ - 1)) * LK + col;
            out[off] = val;
        }
    }
}

__global__ void k_density(float* __restrict__ out) {
    out[(size_t)H * LQ * LK] = (float)g_count / (float)(H * LK);
}

// ---------------------------------------------------------------------------
extern "C" void kernel_launch(void* const* d_in, const int* in_sizes, int n_in,
                              void* d_out, int out_size) {
    const float* scores = (const float*)d_in[0];
    float* out = (float*)d_out;

    k_topk<<<H * LQ, 256>>>(scores, out);   // also zeros the output rows
    k_scan<<<H, 128>>>();
    k_final<<<H, 128>>>();
    k_out<<<dim3(NG, 8), 128>>>(out);
    if (out_size > H * LQ * LK)
        k_density<<<1, 1>>>(out);
}